// round 2
// baseline (speedup 1.0000x reference)
#include <cuda_runtime.h>
#include <cuda_bf16.h>
#include <cstdint>

#define N_NODES 100000
#define N_EDGES 1600000
#define D_IN 128
#define D_HID 128
#define N_CLASSES 64

// ---------------- device scratch (no dynamic alloc allowed) ----------------
__device__ float g_agg[(size_t)N_NODES * D_HID];   // 51.2 MB
__device__ float g_h1 [(size_t)N_NODES * D_HID];   // 51.2 MB
__device__ float g_h2 [(size_t)N_NODES * D_HID];   // 51.2 MB
__device__ float g_deg[N_NODES];                   // deg, then 1/max(deg,1)

// ---------------- helpers ----------------
__device__ __forceinline__ void red_add_v4(float* addr, float4 v) {
    asm volatile("red.global.add.v4.f32 [%0], {%1, %2, %3, %4};"
                 :: "l"(addr), "f"(v.x), "f"(v.y), "f"(v.z), "f"(v.w)
                 : "memory");
}

__device__ __forceinline__ unsigned long long fma2(unsigned long long a,
                                                   unsigned long long b,
                                                   unsigned long long c) {
    unsigned long long d;
    asm("fma.rn.f32x2 %0, %1, %2, %3;" : "=l"(d) : "l"(a), "l"(b), "l"(c));
    return d;
}

__device__ __forceinline__ unsigned long long pack_dup(float x) {
    unsigned long long d;
    asm("mov.b64 %0, {%1, %1};" : "=l"(d) : "f"(x));
    return d;
}

__device__ __forceinline__ void unpack2(unsigned long long v, float& lo, float& hi) {
    asm("mov.b64 {%0, %1}, %2;" : "=f"(lo), "=f"(hi) : "l"(v));
}

// ---------------- small kernels ----------------
__global__ void zero_kernel(int zero_deg) {
    int i = blockIdx.x * blockDim.x + threadIdx.x;
    const int nd4 = N_NODES * D_HID / 4;
    if (i < nd4) reinterpret_cast<float4*>(g_agg)[i] = make_float4(0.f, 0.f, 0.f, 0.f);
    if (zero_deg && i < N_NODES) g_deg[i] = 0.f;
}

__global__ void deg_kernel(const int* __restrict__ dst) {
    int e = blockIdx.x * blockDim.x + threadIdx.x;
    if (e < N_EDGES) atomicAdd(&g_deg[dst[e]], 1.0f);
}

__global__ void invdeg_kernel() {
    int i = blockIdx.x * blockDim.x + threadIdx.x;
    if (i < N_NODES) g_deg[i] = 1.0f / fmaxf(g_deg[i], 1.0f);
}

// One edge per 32 threads; lane c moves one float4 (cols 4c..4c+3).
// Edge indices loaded once per warp and broadcast.
__global__ void scatter_kernel(const float* __restrict__ h,
                               const int* __restrict__ src,
                               const int* __restrict__ dst) {
    unsigned t = blockIdx.x * blockDim.x + threadIdx.x;   // < N_EDGES*32 exactly
    unsigned e = t >> 5;
    unsigned c = t & 31;
    int s = 0, d = 0;
    if (c == 0) { s = __ldg(&src[e]); d = __ldg(&dst[e]); }
    s = __shfl_sync(0xffffffffu, s, 0);
    d = __shfl_sync(0xffffffffu, d, 0);
    float4 v = reinterpret_cast<const float4*>(h)[(size_t)s * 32 + c];
    red_add_v4(&g_agg[(size_t)d * D_HID + c * 4], v);
}

// ---------------- fused GEMM ----------------
// out[BMxBN tile] = act( [X | g_agg*invdeg] @ [W0 ; W1] + bias )
// BM=128, BK=16, TM=8 rows/thread (paired for f32x2), 256 threads.
constexpr int BM = 128;
constexpr int BK = 16;
constexpr int TM = 8;

template<int BN, int TN, bool DUAL, bool RELU>
__global__ __launch_bounds__(256)
void gemm_kernel(const float* __restrict__ X,
                 const float* __restrict__ W0,
                 const float* __restrict__ W1,
                 const float* __restrict__ bias,
                 float* __restrict__ out) {
    __shared__ float As[BK][BM + 2];   // +2 pad: conflict-free stores, keeps 8B align
    __shared__ float Bs[BK][BN];

    const int tid  = threadIdx.x;
    const int trow = tid >> 4;     // 0..15 -> rows trow*8 .. +7
    const int tcol = tid & 15;     // 0..15 -> cols tcol*TN .. +TN-1
    const int rowBase = blockIdx.x * BM;

    unsigned long long acc[TM / 2][TN];
#pragma unroll
    for (int i = 0; i < TM / 2; ++i)
#pragma unroll
        for (int j = 0; j < TN; ++j) acc[i][j] = 0ull;

    const int KTILES = DUAL ? 16 : 8;
    for (int kt = 0; kt < KTILES; ++kt) {
        const bool phase1 = DUAL && (kt >= 8);
        const float* Asrc = phase1 ? g_agg : X;
        const float* Bsrc = phase1 ? W1 : W0;
        const int k0 = (phase1 ? (kt - 8) : kt) * BK;

        // ---- load A tile (128 x 16), transposed into As[k][row]
#pragma unroll
        for (int l = 0; l < 2; ++l) {
            int id = tid + l * 256;          // 0..511
            int r  = id >> 2;                // 0..127
            int c4 = id & 3;                 // 0..3
            int gr = rowBase + r;
            float4 v = make_float4(0.f, 0.f, 0.f, 0.f);
            if (gr < N_NODES) {
                v = *reinterpret_cast<const float4*>(Asrc + (size_t)gr * D_HID + k0 + c4 * 4);
                if (phase1) {
                    float sc = g_deg[gr];
                    v.x *= sc; v.y *= sc; v.z *= sc; v.w *= sc;
                }
            }
            As[c4 * 4 + 0][r] = v.x;
            As[c4 * 4 + 1][r] = v.y;
            As[c4 * 4 + 2][r] = v.z;
            As[c4 * 4 + 3][r] = v.w;
        }

        // ---- load B tile (16 x BN)
        constexpr int BNF4   = BN / 4;
        constexpr int NLOADB = (BK * BNF4 + 255) / 256;
#pragma unroll
        for (int l = 0; l < NLOADB; ++l) {
            int id = tid + l * 256;
            if (id < BK * BNF4) {
                int r = id / BNF4;
                int c = id % BNF4;
                float4 v = *reinterpret_cast<const float4*>(Bsrc + (size_t)(k0 + r) * BN + c * 4);
                *reinterpret_cast<float4*>(&Bs[r][c * 4]) = v;
            }
        }
        __syncthreads();

        // ---- compute
#pragma unroll
        for (int kk = 0; kk < BK; ++kk) {
            const unsigned long long* arow =
                reinterpret_cast<const unsigned long long*>(&As[kk][trow * TM]);
            unsigned long long a2[TM / 2];
#pragma unroll
            for (int i = 0; i < TM / 2; ++i) a2[i] = arow[i];

            unsigned long long b2[TN];
#pragma unroll
            for (int j = 0; j < TN; j += 4) {
                float4 bv = *reinterpret_cast<const float4*>(&Bs[kk][tcol * TN + j]);
                b2[j + 0] = pack_dup(bv.x);
                b2[j + 1] = pack_dup(bv.y);
                b2[j + 2] = pack_dup(bv.z);
                b2[j + 3] = pack_dup(bv.w);
            }
#pragma unroll
            for (int i = 0; i < TM / 2; ++i)
#pragma unroll
                for (int j = 0; j < TN; ++j)
                    acc[i][j] = fma2(a2[i], b2[j], acc[i][j]);
        }
        __syncthreads();
    }

    // ---- epilogue: bias (+relu), store
    float bcol[TN];
#pragma unroll
    for (int j = 0; j < TN; ++j) bcol[j] = bias[tcol * TN + j];

#pragma unroll
    for (int i = 0; i < TM / 2; ++i) {
        float o0[TN], o1[TN];
#pragma unroll
        for (int j = 0; j < TN; ++j) {
            float lo, hi;
            unpack2(acc[i][j], lo, hi);
            lo += bcol[j];
            hi += bcol[j];
            if (RELU) { lo = fmaxf(lo, 0.f); hi = fmaxf(hi, 0.f); }
            o0[j] = lo; o1[j] = hi;
        }
        int r0 = rowBase + trow * TM + 2 * i;
        if (r0 < N_NODES) {
            float* p = out + (size_t)r0 * BN + tcol * TN;
#pragma unroll
            for (int j = 0; j < TN; j += 4)
                *reinterpret_cast<float4*>(p + j) = make_float4(o0[j], o0[j+1], o0[j+2], o0[j+3]);
        }
        if (r0 + 1 < N_NODES) {
            float* p = out + (size_t)(r0 + 1) * BN + tcol * TN;
#pragma unroll
            for (int j = 0; j < TN; j += 4)
                *reinterpret_cast<float4*>(p + j) = make_float4(o1[j], o1[j+1], o1[j+2], o1[j+3]);
        }
    }
}

// Writers into device globals (avoid host symbol-address lookups entirely)
__global__ void noop_kernel() {}

// ---------------- launch ----------------
extern "C" void kernel_launch(void* const* d_in, const int* in_sizes, int n_in,
                              void* d_out, int out_size) {
    const float* feat = (const float*)d_in[0];
    const int*   src  = (const int*)  d_in[1];
    const int*   dst  = (const int*)  d_in[2];
    const float* Ws1  = (const float*)d_in[3];
    const float* Wn1  = (const float*)d_in[4];
    const float* b1   = (const float*)d_in[5];
    const float* Ws2  = (const float*)d_in[6];
    const float* Wn2  = (const float*)d_in[7];
    const float* b2   = (const float*)d_in[8];
    const float* Wout = (const float*)d_in[9];
    const float* bout = (const float*)d_in[10];
    float* out = (float*)d_out;

    // h1/h2 addresses: device globals referenced by name inside kernels isn't
    // possible for the 'out'/'X' parameters without symbol lookup, so do the
    // one legal lookup (pure address query; no allocation, no stream work).
    static float* h1 = nullptr;
    static float* h2 = nullptr;
    if (!h1) {
        cudaGetSymbolAddress((void**)&h1, g_h1);
        cudaGetSymbolAddress((void**)&h2, g_h2);
    }

    const int ZB  = (N_NODES * D_HID / 4 + 255) / 256;   // zero blocks
    const int DB  = (N_EDGES + 255) / 256;
    const int IB  = (N_NODES + 255) / 256;
    const int SB  = N_EDGES * 32 / 256;                  // 200000 (exact)
    const int GB  = (N_NODES + BM - 1) / BM;             // 782

    // degree (reused by both layers)
    zero_kernel<<<ZB, 256>>>(1);
    deg_kernel<<<DB, 256>>>(dst);
    invdeg_kernel<<<IB, 256>>>();

    // layer 1
    scatter_kernel<<<SB, 256>>>(feat, src, dst);
    gemm_kernel<128, 8, true, true><<<GB, 256>>>(feat, Ws1, Wn1, b1, h1);

    // layer 2
    zero_kernel<<<ZB, 256>>>(0);
    scatter_kernel<<<SB, 256>>>(h1, src, dst);
    gemm_kernel<128, 8, true, true><<<GB, 256>>>(h1, Ws2, Wn2, b2, h2);

    // output projection
    gemm_kernel<64, 4, false, false><<<GB, 256>>>(h2, Wout, nullptr, bout, out);
}

// round 3
// speedup vs baseline: 1.0956x; 1.0956x over previous
#include <cuda_runtime.h>
#include <cuda_bf16.h>
#include <cstdint>

#define N_NODES 100000
#define N_EDGES 1600000
#define D_IN 128
#define D_HID 128
#define N_CLASSES 64

// ---------------- device scratch (no dynamic alloc allowed) ----------------
__device__ float    g_agg [(size_t)N_NODES * D_HID];   // 51.2 MB
__device__ float    g_h1  [(size_t)N_NODES * D_HID];   // 51.2 MB
__device__ float    g_h2  [(size_t)N_NODES * D_HID];   // 51.2 MB
__device__ float    g_inv [N_NODES];                   // 1/max(deg,1)
__device__ unsigned g_ideg[N_NODES];                   // int degree
__device__ unsigned g_off [N_NODES + 1];               // CSR row offsets
__device__ unsigned g_cur [N_NODES];                   // fill cursors
__device__ int      g_esrc[N_EDGES];                   // src ids sorted by dst

// ---------------- helpers ----------------
__device__ __forceinline__ unsigned long long fma2(unsigned long long a,
                                                   unsigned long long b,
                                                   unsigned long long c) {
    unsigned long long d;
    asm("fma.rn.f32x2 %0, %1, %2, %3;" : "=l"(d) : "l"(a), "l"(b), "l"(c));
    return d;
}

__device__ __forceinline__ unsigned long long pack_dup(float x) {
    unsigned long long d;
    asm("mov.b64 %0, {%1, %1};" : "=l"(d) : "f"(x));
    return d;
}

__device__ __forceinline__ void unpack2(unsigned long long v, float& lo, float& hi) {
    asm("mov.b64 {%0, %1}, %2;" : "=f"(lo), "=f"(hi) : "l"(v));
}

// ---------------- CSR build ----------------
__global__ void zero_ideg_kernel() {
    int i = blockIdx.x * blockDim.x + threadIdx.x;
    if (i < N_NODES) g_ideg[i] = 0u;
}

__global__ void deg_kernel(const int* __restrict__ dst) {
    int e = blockIdx.x * blockDim.x + threadIdx.x;
    if (e < N_EDGES) atomicAdd(&g_ideg[dst[e]], 1u);
}

// Single-block (1024 threads) exclusive scan over 100k degrees.
// Also writes fill cursors and inverse degrees.
__global__ __launch_bounds__(1024)
void scan_kernel() {
    __shared__ unsigned sm[1024];
    const int t  = threadIdx.x;
    const int CH = (N_NODES + 1023) / 1024;            // 98
    int lo = t * CH;
    int hi = lo + CH; if (hi > N_NODES) hi = N_NODES;
    if (lo > N_NODES) lo = N_NODES;

    unsigned sum = 0;
    for (int i = lo; i < hi; ++i) sum += g_ideg[i];
    sm[t] = sum;
    __syncthreads();

    // Hillis-Steele inclusive scan over 1024 partials
    for (int d = 1; d < 1024; d <<= 1) {
        unsigned u = (t >= d) ? sm[t - d] : 0u;
        __syncthreads();
        sm[t] += u;
        __syncthreads();
    }

    unsigned off = sm[t] - sum;                        // exclusive prefix
    for (int i = lo; i < hi; ++i) {
        unsigned d = g_ideg[i];
        g_off[i] = off;
        g_cur[i] = off;
        g_inv[i] = 1.0f / fmaxf((float)d, 1.0f);
        off += d;
    }
    if (t == 1023) g_off[N_NODES] = sm[1023];
}

__global__ void fill_kernel(const int* __restrict__ src,
                            const int* __restrict__ dst) {
    int e = blockIdx.x * blockDim.x + threadIdx.x;
    if (e < N_EDGES) {
        unsigned p = atomicAdd(&g_cur[dst[e]], 1u);
        g_esrc[p] = src[e];
    }
}

// ---------------- gather-mean: one warp per dst node ----------------
__global__ __launch_bounds__(256)
void gather_kernel(const float* __restrict__ h) {
    unsigned warp = (blockIdx.x * blockDim.x + threadIdx.x) >> 5;
    if (warp >= N_NODES) return;
    const unsigned lane = threadIdx.x & 31;

    unsigned start = g_off[warp];
    unsigned end   = g_off[warp + 1];

    float4 a0 = make_float4(0.f, 0.f, 0.f, 0.f);
    float4 a1 = make_float4(0.f, 0.f, 0.f, 0.f);
    float4 a2 = make_float4(0.f, 0.f, 0.f, 0.f);
    float4 a3 = make_float4(0.f, 0.f, 0.f, 0.f);

    const float4* __restrict__ hv = reinterpret_cast<const float4*>(h);
    unsigned i = start;
    for (; i + 4 <= end; i += 4) {
        int s0 = __ldg(&g_esrc[i + 0]);
        int s1 = __ldg(&g_esrc[i + 1]);
        int s2 = __ldg(&g_esrc[i + 2]);
        int s3 = __ldg(&g_esrc[i + 3]);
        float4 v0 = hv[(size_t)s0 * 32 + lane];
        float4 v1 = hv[(size_t)s1 * 32 + lane];
        float4 v2 = hv[(size_t)s2 * 32 + lane];
        float4 v3 = hv[(size_t)s3 * 32 + lane];
        a0.x += v0.x; a0.y += v0.y; a0.z += v0.z; a0.w += v0.w;
        a1.x += v1.x; a1.y += v1.y; a1.z += v1.z; a1.w += v1.w;
        a2.x += v2.x; a2.y += v2.y; a2.z += v2.z; a2.w += v2.w;
        a3.x += v3.x; a3.y += v3.y; a3.z += v3.z; a3.w += v3.w;
    }
    for (; i < end; ++i) {
        int s = __ldg(&g_esrc[i]);
        float4 v = hv[(size_t)s * 32 + lane];
        a0.x += v.x; a0.y += v.y; a0.z += v.z; a0.w += v.w;
    }

    float sc = g_inv[warp];
    float4 r;
    r.x = (a0.x + a1.x + a2.x + a3.x) * sc;
    r.y = (a0.y + a1.y + a2.y + a3.y) * sc;
    r.z = (a0.z + a1.z + a2.z + a3.z) * sc;
    r.w = (a0.w + a1.w + a2.w + a3.w) * sc;
    reinterpret_cast<float4*>(g_agg)[(size_t)warp * 32 + lane] = r;
}

// ---------------- fused GEMM ----------------
// out[BMxBN tile] = act( [X | g_agg] @ [W0 ; W1] + bias )   (g_agg pre-scaled)
constexpr int BM = 128;
constexpr int BK = 16;
constexpr int TM = 8;

template<int BN, int TN, bool DUAL, bool RELU>
__global__ __launch_bounds__(256)
void gemm_kernel(const float* __restrict__ X,
                 const float* __restrict__ W0,
                 const float* __restrict__ W1,
                 const float* __restrict__ bias,
                 float* __restrict__ out) {
    __shared__ float As[BK][BM + 2];
    __shared__ float Bs[BK][BN];

    const int tid  = threadIdx.x;
    const int trow = tid >> 4;
    const int tcol = tid & 15;
    const int rowBase = blockIdx.x * BM;

    unsigned long long acc[TM / 2][TN];
#pragma unroll
    for (int i = 0; i < TM / 2; ++i)
#pragma unroll
        for (int j = 0; j < TN; ++j) acc[i][j] = 0ull;

    const int KTILES = DUAL ? 16 : 8;
    for (int kt = 0; kt < KTILES; ++kt) {
        const bool phase1 = DUAL && (kt >= 8);
        const float* Asrc = phase1 ? g_agg : X;
        const float* Bsrc = phase1 ? W1 : W0;
        const int k0 = (phase1 ? (kt - 8) : kt) * BK;

        // ---- load A tile (128 x 16), transposed into As[k][row]
#pragma unroll
        for (int l = 0; l < 2; ++l) {
            int id = tid + l * 256;
            int r  = id >> 2;
            int c4 = id & 3;
            int gr = rowBase + r;
            float4 v = make_float4(0.f, 0.f, 0.f, 0.f);
            if (gr < N_NODES)
                v = *reinterpret_cast<const float4*>(Asrc + (size_t)gr * D_HID + k0 + c4 * 4);
            As[c4 * 4 + 0][r] = v.x;
            As[c4 * 4 + 1][r] = v.y;
            As[c4 * 4 + 2][r] = v.z;
            As[c4 * 4 + 3][r] = v.w;
        }

        // ---- load B tile (16 x BN)
        constexpr int BNF4   = BN / 4;
        constexpr int NLOADB = (BK * BNF4 + 255) / 256;
#pragma unroll
        for (int l = 0; l < NLOADB; ++l) {
            int id = tid + l * 256;
            if (id < BK * BNF4) {
                int r = id / BNF4;
                int c = id % BNF4;
                float4 v = *reinterpret_cast<const float4*>(Bsrc + (size_t)(k0 + r) * BN + c * 4);
                *reinterpret_cast<float4*>(&Bs[r][c * 4]) = v;
            }
        }
        __syncthreads();

        // ---- compute
#pragma unroll
        for (int kk = 0; kk < BK; ++kk) {
            const unsigned long long* arow =
                reinterpret_cast<const unsigned long long*>(&As[kk][trow * TM]);
            unsigned long long a2[TM / 2];
#pragma unroll
            for (int i = 0; i < TM / 2; ++i) a2[i] = arow[i];

            unsigned long long b2[TN];
#pragma unroll
            for (int j = 0; j < TN; j += 4) {
                float4 bv = *reinterpret_cast<const float4*>(&Bs[kk][tcol * TN + j]);
                b2[j + 0] = pack_dup(bv.x);
                b2[j + 1] = pack_dup(bv.y);
                b2[j + 2] = pack_dup(bv.z);
                b2[j + 3] = pack_dup(bv.w);
            }
#pragma unroll
            for (int i = 0; i < TM / 2; ++i)
#pragma unroll
                for (int j = 0; j < TN; ++j)
                    acc[i][j] = fma2(a2[i], b2[j], acc[i][j]);
        }
        __syncthreads();
    }

    // ---- epilogue
    float bcol[TN];
#pragma unroll
    for (int j = 0; j < TN; ++j) bcol[j] = bias[tcol * TN + j];

#pragma unroll
    for (int i = 0; i < TM / 2; ++i) {
        float o0[TN], o1[TN];
#pragma unroll
        for (int j = 0; j < TN; ++j) {
            float lo, hi;
            unpack2(acc[i][j], lo, hi);
            lo += bcol[j];
            hi += bcol[j];
            if (RELU) { lo = fmaxf(lo, 0.f); hi = fmaxf(hi, 0.f); }
            o0[j] = lo; o1[j] = hi;
        }
        int r0 = rowBase + trow * TM + 2 * i;
        if (r0 < N_NODES) {
            float* p = out + (size_t)r0 * BN + tcol * TN;
#pragma unroll
            for (int j = 0; j < TN; j += 4)
                *reinterpret_cast<float4*>(p + j) = make_float4(o0[j], o0[j+1], o0[j+2], o0[j+3]);
        }
        if (r0 + 1 < N_NODES) {
            float* p = out + (size_t)(r0 + 1) * BN + tcol * TN;
#pragma unroll
            for (int j = 0; j < TN; j += 4)
                *reinterpret_cast<float4*>(p + j) = make_float4(o1[j], o1[j+1], o1[j+2], o1[j+3]);
        }
    }
}

// ---------------- launch ----------------
extern "C" void kernel_launch(void* const* d_in, const int* in_sizes, int n_in,
                              void* d_out, int out_size) {
    const float* feat = (const float*)d_in[0];
    const int*   src  = (const int*)  d_in[1];
    const int*   dst  = (const int*)  d_in[2];
    const float* Ws1  = (const float*)d_in[3];
    const float* Wn1  = (const float*)d_in[4];
    const float* b1   = (const float*)d_in[5];
    const float* Ws2  = (const float*)d_in[6];
    const float* Wn2  = (const float*)d_in[7];
    const float* b2   = (const float*)d_in[8];
    const float* Wout = (const float*)d_in[9];
    const float* bout = (const float*)d_in[10];
    float* out = (float*)d_out;

    static float* h1 = nullptr;
    static float* h2 = nullptr;
    if (!h1) {
        cudaGetSymbolAddress((void**)&h1, g_h1);
        cudaGetSymbolAddress((void**)&h2, g_h2);
    }

    const int IB = (N_NODES + 255) / 256;
    const int EB = (N_EDGES + 255) / 256;
    const int GAB = (N_NODES * 32 + 255) / 256;          // gather: warp per node
    const int GB  = (N_NODES + BM - 1) / BM;             // 782

    // CSR build (per call; deterministic work, order-free results)
    zero_ideg_kernel<<<IB, 256>>>();
    deg_kernel<<<EB, 256>>>(dst);
    scan_kernel<<<1, 1024>>>();
    fill_kernel<<<EB, 256>>>(src, dst);

    // layer 1
    gather_kernel<<<GAB, 256>>>(feat);
    gemm_kernel<128, 8, true, true><<<GB, 256>>>(feat, Ws1, Wn1, b1, h1);

    // layer 2
    gather_kernel<<<GAB, 256>>>(h1);
    gemm_kernel<128, 8, true, true><<<GB, 256>>>(h1, Ws2, Wn2, b2, h2);

    // output projection
    gemm_kernel<64, 4, false, false><<<GB, 256>>>(h2, Wout, nullptr, bout, out);
}

// round 6
// speedup vs baseline: 1.2044x; 1.0993x over previous
#include <cuda_runtime.h>
#include <cuda_bf16.h>
#include <cstdint>

#define N_NODES 100000
#define N_EDGES 1600000
#define D_IN 128
#define D_HID 128
#define N_CLASSES 64

// ---------------- device scratch (no dynamic alloc) ----------------
__device__ float    g_h1  [(size_t)N_NODES * D_HID];        // fp32 h1 (gather2 input)
__device__ __align__(16) __nv_bfloat16 g_feat_hi[(size_t)N_NODES * D_IN];
__device__ __align__(16) __nv_bfloat16 g_feat_lo[(size_t)N_NODES * D_IN];
__device__ __align__(16) __nv_bfloat16 g_agg_hi [(size_t)N_NODES * D_HID];
__device__ __align__(16) __nv_bfloat16 g_agg_lo [(size_t)N_NODES * D_HID];
__device__ __align__(16) __nv_bfloat16 g_h1_hi  [(size_t)N_NODES * D_HID];
__device__ __align__(16) __nv_bfloat16 g_h1_lo  [(size_t)N_NODES * D_HID];
__device__ __align__(16) __nv_bfloat16 g_h2_hi  [(size_t)N_NODES * D_HID];
__device__ __align__(16) __nv_bfloat16 g_h2_lo  [(size_t)N_NODES * D_HID];
// transposed split weights, B[n][k]  (K=256 for layers, 128 for out)
__device__ __align__(16) __nv_bfloat16 g_B1_hi[128 * 256];
__device__ __align__(16) __nv_bfloat16 g_B1_lo[128 * 256];
__device__ __align__(16) __nv_bfloat16 g_B2_hi[128 * 256];
__device__ __align__(16) __nv_bfloat16 g_B2_lo[128 * 256];
__device__ __align__(16) __nv_bfloat16 g_Bo_hi[64 * 128];
__device__ __align__(16) __nv_bfloat16 g_Bo_lo[64 * 128];
// CSR
__device__ float    g_inv [N_NODES];
__device__ unsigned g_ideg[N_NODES];
__device__ unsigned g_off [N_NODES + 1];
__device__ unsigned g_cur [N_NODES];
__device__ int      g_esrc[N_EDGES];

// ---------------- helpers ----------------
__device__ __forceinline__ uint32_t smem_to_u32(const void* p) {
    uint32_t a;
    asm("{ .reg .u64 t; cvta.to.shared.u64 t, %1; cvt.u32.u64 %0, t; }" : "=r"(a) : "l"(p));
    return a;
}

__device__ __forceinline__ void ldsm_x4(uint32_t addr, uint32_t* r) {
    asm volatile("ldmatrix.sync.aligned.m8n8.x4.shared.b16 {%0,%1,%2,%3}, [%4];"
                 : "=r"(r[0]), "=r"(r[1]), "=r"(r[2]), "=r"(r[3]) : "r"(addr));
}

__device__ __forceinline__ void mma16816(float* c, const uint32_t* a,
                                         uint32_t b0, uint32_t b1) {
    asm volatile("mma.sync.aligned.m16n8k16.row.col.f32.bf16.bf16.f32 "
                 "{%0,%1,%2,%3}, {%4,%5,%6,%7}, {%8,%9}, {%0,%1,%2,%3};"
                 : "+f"(c[0]), "+f"(c[1]), "+f"(c[2]), "+f"(c[3])
                 : "r"(a[0]), "r"(a[1]), "r"(a[2]), "r"(a[3]), "r"(b0), "r"(b1));
}

__device__ __forceinline__ void split_bf16(float v, __nv_bfloat16& hi, __nv_bfloat16& lo) {
    hi = __float2bfloat16(v);
    lo = __float2bfloat16(v - __bfloat162float(hi));
}

// ---------------- CSR build ----------------
__global__ void zero_ideg_kernel() {
    int i = blockIdx.x * blockDim.x + threadIdx.x;
    if (i < N_NODES) g_ideg[i] = 0u;
}
__global__ void deg_kernel(const int* __restrict__ dst) {
    int e = blockIdx.x * blockDim.x + threadIdx.x;
    if (e < N_EDGES) atomicAdd(&g_ideg[dst[e]], 1u);
}
__global__ __launch_bounds__(1024)
void scan_kernel() {
    __shared__ unsigned sm[1024];
    const int t  = threadIdx.x;
    const int CH = (N_NODES + 1023) / 1024;
    int lo = t * CH;
    int hi = lo + CH; if (hi > N_NODES) hi = N_NODES;
    if (lo > N_NODES) lo = N_NODES;
    unsigned sum = 0;
    for (int i = lo; i < hi; ++i) sum += g_ideg[i];
    sm[t] = sum;
    __syncthreads();
    for (int d = 1; d < 1024; d <<= 1) {
        unsigned u = (t >= d) ? sm[t - d] : 0u;
        __syncthreads();
        sm[t] += u;
        __syncthreads();
    }
    unsigned off = sm[t] - sum;
    for (int i = lo; i < hi; ++i) {
        unsigned d = g_ideg[i];
        g_off[i] = off;
        g_cur[i] = off;
        g_inv[i] = 1.0f / fmaxf((float)d, 1.0f);
        off += d;
    }
    if (t == 1023) g_off[N_NODES] = sm[1023];
}
__global__ void fill_kernel(const int* __restrict__ src, const int* __restrict__ dst) {
    int e = blockIdx.x * blockDim.x + threadIdx.x;
    if (e < N_EDGES) {
        unsigned p = atomicAdd(&g_cur[dst[e]], 1u);
        g_esrc[p] = src[e];
    }
}

// ---------------- input/weight prep ----------------
__global__ void fconv_kernel(const float* __restrict__ f) {
    unsigned i = blockIdx.x * blockDim.x + threadIdx.x;   // over N_NODES*32 float4 units
    if (i >= (unsigned)N_NODES * 32u) return;
    float4 v = reinterpret_cast<const float4*>(f)[i];
    __nv_bfloat16 hx, lx, hy, ly, hz, lz, hw, lw;
    split_bf16(v.x, hx, lx); split_bf16(v.y, hy, ly);
    split_bf16(v.z, hz, lz); split_bf16(v.w, hw, lw);
    __nv_bfloat162 H0; H0.x = hx; H0.y = hy;
    __nv_bfloat162 H1; H1.x = hz; H1.y = hw;
    __nv_bfloat162 L0; L0.x = lx; L0.y = ly;
    __nv_bfloat162 L1; L1.x = lz; L1.y = lw;
    reinterpret_cast<__nv_bfloat162*>(g_feat_hi)[i * 2 + 0] = H0;
    reinterpret_cast<__nv_bfloat162*>(g_feat_hi)[i * 2 + 1] = H1;
    reinterpret_cast<__nv_bfloat162*>(g_feat_lo)[i * 2 + 0] = L0;
    reinterpret_cast<__nv_bfloat162*>(g_feat_lo)[i * 2 + 1] = L1;
}

__global__ void wprep_kernel(const float* __restrict__ Ws1, const float* __restrict__ Wn1,
                             const float* __restrict__ Ws2, const float* __restrict__ Wn2,
                             const float* __restrict__ Wo) {
    int i = blockIdx.x * blockDim.x + threadIdx.x;
    float v; __nv_bfloat16 *dh, *dl; int idx;
    if (i < 32768) {
        int n = i >> 8, k = i & 255;
        v = (k < 128) ? Ws1[k * 128 + n] : Wn1[(k - 128) * 128 + n];
        dh = g_B1_hi; dl = g_B1_lo; idx = i;
    } else if (i < 65536) {
        int j = i - 32768; int n = j >> 8, k = j & 255;
        v = (k < 128) ? Ws2[k * 128 + n] : Wn2[(k - 128) * 128 + n];
        dh = g_B2_hi; dl = g_B2_lo; idx = j;
    } else if (i < 73728) {
        int j = i - 65536; int n = j >> 7, k = j & 127;
        v = Wo[k * 64 + n];
        dh = g_Bo_hi; dl = g_Bo_lo; idx = j;
    } else return;
    __nv_bfloat16 h, l;
    split_bf16(v, h, l);
    dh[idx] = h; dl[idx] = l;
}

// ---------------- gather-mean: one warp per dst node, bf16-split output -----
__global__ __launch_bounds__(256)
void gather_kernel(const float* __restrict__ h) {
    unsigned warp = (blockIdx.x * blockDim.x + threadIdx.x) >> 5;
    if (warp >= N_NODES) return;
    const unsigned lane = threadIdx.x & 31;
    unsigned start = g_off[warp];
    unsigned end   = g_off[warp + 1];

    float4 a0 = make_float4(0.f, 0.f, 0.f, 0.f);
    float4 a1 = make_float4(0.f, 0.f, 0.f, 0.f);
    float4 a2 = make_float4(0.f, 0.f, 0.f, 0.f);
    float4 a3 = make_float4(0.f, 0.f, 0.f, 0.f);
    const float4* __restrict__ hv = reinterpret_cast<const float4*>(h);
    unsigned i = start;
    for (; i + 4 <= end; i += 4) {
        int s0 = __ldg(&g_esrc[i + 0]);
        int s1 = __ldg(&g_esrc[i + 1]);
        int s2 = __ldg(&g_esrc[i + 2]);
        int s3 = __ldg(&g_esrc[i + 3]);
        float4 v0 = hv[(size_t)s0 * 32 + lane];
        float4 v1 = hv[(size_t)s1 * 32 + lane];
        float4 v2 = hv[(size_t)s2 * 32 + lane];
        float4 v3 = hv[(size_t)s3 * 32 + lane];
        a0.x += v0.x; a0.y += v0.y; a0.z += v0.z; a0.w += v0.w;
        a1.x += v1.x; a1.y += v1.y; a1.z += v1.z; a1.w += v1.w;
        a2.x += v2.x; a2.y += v2.y; a2.z += v2.z; a2.w += v2.w;
        a3.x += v3.x; a3.y += v3.y; a3.z += v3.z; a3.w += v3.w;
    }
    for (; i < end; ++i) {
        int s = __ldg(&g_esrc[i]);
        float4 v = hv[(size_t)s * 32 + lane];
        a0.x += v.x; a0.y += v.y; a0.z += v.z; a0.w += v.w;
    }
    float sc = g_inv[warp];
    float rx = (a0.x + a1.x + a2.x + a3.x) * sc;
    float ry = (a0.y + a1.y + a2.y + a3.y) * sc;
    float rz = (a0.z + a1.z + a2.z + a3.z) * sc;
    float rw = (a0.w + a1.w + a2.w + a3.w) * sc;

    __nv_bfloat16 hx, lx, hy, ly, hz, lz, hw, lw;
    split_bf16(rx, hx, lx); split_bf16(ry, hy, ly);
    split_bf16(rz, hz, lz); split_bf16(rw, hw, lw);
    size_t base = (size_t)warp * D_HID + lane * 4;
    __nv_bfloat162 H0; H0.x = hx; H0.y = hy;
    __nv_bfloat162 H1; H1.x = hz; H1.y = hw;
    __nv_bfloat162 L0; L0.x = lx; L0.y = ly;
    __nv_bfloat162 L1; L1.x = lz; L1.y = lw;
    *reinterpret_cast<__nv_bfloat162*>(g_agg_hi + base)     = H0;
    *reinterpret_cast<__nv_bfloat162*>(g_agg_hi + base + 2) = H1;
    *reinterpret_cast<__nv_bfloat162*>(g_agg_lo + base)     = L0;
    *reinterpret_cast<__nv_bfloat162*>(g_agg_lo + base + 2) = L1;
}

// ---------------- mma.sync split-bf16 GEMM ----------------
// C[128 x BN] = sum over NCHUNKS chunks of 64 K-cols: Ah*Bh + Ah*Bl + Al*Bh
// DUALSRC: chunks 0-1 from (A_hi,A_lo), chunks 2-3 from g_agg_hi/lo.
// 512 threads = 16 warps; warp tile 32x32; smem rows padded to 144B.
constexpr int ROWB = 144;                       // 64 bf16 (128B) + 16B pad
constexpr int smem_bytes(int BN) { return 2 * 128 * ROWB + 2 * BN * ROWB; }

template<int BN, int NCHUNKS, bool DUALSRC, bool WF32, bool WBF16, bool RELU>
__global__ __launch_bounds__(512)
void mma_gemm_kernel(const __nv_bfloat16* __restrict__ A_hi,
                     const __nv_bfloat16* __restrict__ A_lo,
                     const __nv_bfloat16* __restrict__ B_hi,
                     const __nv_bfloat16* __restrict__ B_lo,
                     const float* __restrict__ bias,
                     float* __restrict__ outf,
                     __nv_bfloat16* __restrict__ out_hi,
                     __nv_bfloat16* __restrict__ out_lo) {
    extern __shared__ unsigned char dynsm[];
    constexpr int OFF_A_HI = 0;
    constexpr int OFF_A_LO = 128 * ROWB;
    constexpr int OFF_B_HI = 2 * 128 * ROWB;
    constexpr int OFF_B_LO = OFF_B_HI + BN * ROWB;
    constexpr int KTOT = NCHUNKS * 64;
    constexpr int NW = BN / 32;                 // warps along N

    const int tid  = threadIdx.x;
    const int wid  = tid >> 5;
    const int lane = tid & 31;
    const int rowBase = blockIdx.x * 128;
    const uint32_t sbase = smem_to_u32(dynsm);

    const bool active = wid < 4 * NW;
    const int warpM = wid / NW;                 // 0..3
    const int warpN = wid % NW;                 // 0..NW-1

    float acc[2][4][4];
#pragma unroll
    for (int mi = 0; mi < 2; ++mi)
#pragma unroll
        for (int j = 0; j < 4; ++j)
#pragma unroll
            for (int c = 0; c < 4; ++c) acc[mi][j][c] = 0.f;

    // per-lane ldmatrix row mapping: m = lane/8, r = lane%8
    const int lm_m = lane >> 3;
    const int lm_r = lane & 7;
    const int lm_rowoff = (lm_m & 1) * 8 + lm_r;     // row within 16-row tile
    const int lm_coloff = (lm_m >> 1) * 16;          // byte offset within k16

    for (int ch = 0; ch < NCHUNKS; ++ch) {
        // ---- stage A chunk (128 x 64 bf16 hi/lo)
        for (int u = tid; u < 1024; u += 512) {
            int r = u >> 3, c = u & 7;
            int gr = rowBase + r;
            uint4 vh = make_uint4(0, 0, 0, 0), vl = make_uint4(0, 0, 0, 0);
            if (gr < N_NODES) {
                const __nv_bfloat16 *ph, *pl;
                size_t off;
                if (!DUALSRC || ch < 2) {
                    off = (size_t)gr * 128 + ch * 64 + c * 8;
                    ph = A_hi; pl = A_lo;
                } else {
                    off = (size_t)gr * 128 + (ch - 2) * 64 + c * 8;
                    ph = g_agg_hi; pl = g_agg_lo;
                }
                vh = *reinterpret_cast<const uint4*>(ph + off);
                vl = *reinterpret_cast<const uint4*>(pl + off);
            }
            *reinterpret_cast<uint4*>(dynsm + OFF_A_HI + r * ROWB + c * 16) = vh;
            *reinterpret_cast<uint4*>(dynsm + OFF_A_LO + r * ROWB + c * 16) = vl;
        }
        // ---- stage B chunk (BN x 64 bf16 hi/lo), source layout [n][KTOT]
        for (int u = tid; u < BN * 8; u += 512) {
            int n = u >> 3, c = u & 7;
            size_t off = (size_t)n * KTOT + ch * 64 + c * 8;
            *reinterpret_cast<uint4*>(dynsm + OFF_B_HI + n * ROWB + c * 16) =
                *reinterpret_cast<const uint4*>(B_hi + off);
            *reinterpret_cast<uint4*>(dynsm + OFF_B_LO + n * ROWB + c * 16) =
                *reinterpret_cast<const uint4*>(B_lo + off);
        }
        __syncthreads();

        if (active) {
#pragma unroll
            for (int ks = 0; ks < 4; ++ks) {
                const int kb = ks * 32 + lm_coloff;       // byte offset in row
                uint32_t ah[2][4], al[2][4];
#pragma unroll
                for (int mi = 0; mi < 2; ++mi) {
                    int row = warpM * 32 + mi * 16 + lm_rowoff;
                    ldsm_x4(sbase + OFF_A_HI + row * ROWB + kb, ah[mi]);
                    ldsm_x4(sbase + OFF_A_LO + row * ROWB + kb, al[mi]);
                }
                uint32_t bh[2][4], bl[2][4];
#pragma unroll
                for (int nb = 0; nb < 2; ++nb) {
                    int nrow = warpN * 32 + nb * 16 + lm_rowoff;
                    ldsm_x4(sbase + OFF_B_HI + nrow * ROWB + kb, bh[nb]);
                    ldsm_x4(sbase + OFF_B_LO + nrow * ROWB + kb, bl[nb]);
                }
#pragma unroll
                for (int mi = 0; mi < 2; ++mi)
#pragma unroll
                    for (int j = 0; j < 4; ++j) {
                        const int nb = j >> 1, jj = j & 1;
                        mma16816(acc[mi][j], ah[mi], bh[nb][jj], bh[nb][jj + 2]);
                        mma16816(acc[mi][j], ah[mi], bl[nb][jj], bl[nb][jj + 2]);
                        mma16816(acc[mi][j], al[mi], bh[nb][jj], bh[nb][jj + 2]);
                    }
            }
        }
        __syncthreads();
    }

    // ---- epilogue
    if (active) {
        const int rlo  = rowBase + warpM * 32 + (lane >> 2);
        const int colw = warpN * 32 + 2 * (lane & 3);
#pragma unroll
        for (int mi = 0; mi < 2; ++mi) {
#pragma unroll
            for (int j = 0; j < 4; ++j) {
                const int col = colw + j * 8;
                const float b0 = __ldg(&bias[col]);
                const float b1 = __ldg(&bias[col + 1]);
#pragma unroll
                for (int half = 0; half < 2; ++half) {
                    int r = rlo + mi * 16 + half * 8;
                    if (r >= N_NODES) continue;
                    float v0 = acc[mi][j][2 * half + 0] + b0;
                    float v1 = acc[mi][j][2 * half + 1] + b1;
                    if (RELU) { v0 = fmaxf(v0, 0.f); v1 = fmaxf(v1, 0.f); }
                    if (WF32) {
                        float2 f2; f2.x = v0; f2.y = v1;
                        *reinterpret_cast<float2*>(outf + (size_t)r * BN + col) = f2;
                    }
                    if (WBF16) {
                        __nv_bfloat16 h0, l0, h1, l1;
                        split_bf16(v0, h0, l0);
                        split_bf16(v1, h1, l1);
                        __nv_bfloat162 H; H.x = h0; H.y = h1;
                        __nv_bfloat162 L; L.x = l0; L.y = l1;
                        *reinterpret_cast<__nv_bfloat162*>(out_hi + (size_t)r * BN + col) = H;
                        *reinterpret_cast<__nv_bfloat162*>(out_lo + (size_t)r * BN + col) = L;
                    }
                }
            }
        }
    }
}

// ---------------- launch ----------------
extern "C" void kernel_launch(void* const* d_in, const int* in_sizes, int n_in,
                              void* d_out, int out_size) {
    const float* feat = (const float*)d_in[0];
    const int*   src  = (const int*)  d_in[1];
    const int*   dst  = (const int*)  d_in[2];
    const float* Ws1  = (const float*)d_in[3];
    const float* Wn1  = (const float*)d_in[4];
    const float* b1   = (const float*)d_in[5];
    const float* Ws2  = (const float*)d_in[6];
    const float* Wn2  = (const float*)d_in[7];
    const float* b2   = (const float*)d_in[8];
    const float* Wout = (const float*)d_in[9];
    const float* bout = (const float*)d_in[10];
    float* out = (float*)d_out;

    float* h1;
    __nv_bfloat16 *p_feat_hi, *p_feat_lo, *p_h1_hi, *p_h1_lo, *p_h2_hi, *p_h2_lo;
    __nv_bfloat16 *p_B1_hi, *p_B1_lo, *p_B2_hi, *p_B2_lo, *p_Bo_hi, *p_Bo_lo;
    cudaGetSymbolAddress((void**)&h1, g_h1);
    cudaGetSymbolAddress((void**)&p_feat_hi, g_feat_hi);
    cudaGetSymbolAddress((void**)&p_feat_lo, g_feat_lo);
    cudaGetSymbolAddress((void**)&p_h1_hi, g_h1_hi);
    cudaGetSymbolAddress((void**)&p_h1_lo, g_h1_lo);
    cudaGetSymbolAddress((void**)&p_h2_hi, g_h2_hi);
    cudaGetSymbolAddress((void**)&p_h2_lo, g_h2_lo);
    cudaGetSymbolAddress((void**)&p_B1_hi, g_B1_hi);
    cudaGetSymbolAddress((void**)&p_B1_lo, g_B1_lo);
    cudaGetSymbolAddress((void**)&p_B2_hi, g_B2_hi);
    cudaGetSymbolAddress((void**)&p_B2_lo, g_B2_lo);
    cudaGetSymbolAddress((void**)&p_Bo_hi, g_Bo_hi);
    cudaGetSymbolAddress((void**)&p_Bo_lo, g_Bo_lo);
    cudaFuncSetAttribute(mma_gemm_kernel<128, 4, true, true,  true,  true>,
                         cudaFuncAttributeMaxDynamicSharedMemorySize, smem_bytes(128));
    cudaFuncSetAttribute(mma_gemm_kernel<128, 4, true, false, true,  true>,
                         cudaFuncAttributeMaxDynamicSharedMemorySize, smem_bytes(128));
    cudaFuncSetAttribute(mma_gemm_kernel<64, 2, false, true,  false, false>,
                         cudaFuncAttributeMaxDynamicSharedMemorySize, smem_bytes(64));

    const int IB  = (N_NODES + 255) / 256;
    const int EB  = (N_EDGES + 255) / 256;
    const int GAB = (N_NODES * 32 + 255) / 256;
    const int GB  = (N_NODES + 127) / 128;               // 782
    const int FCB = (N_NODES * 32 + 255) / 256;

    // CSR build
    zero_ideg_kernel<<<IB, 256>>>();
    deg_kernel<<<EB, 256>>>(dst);
    scan_kernel<<<1, 1024>>>();
    fill_kernel<<<EB, 256>>>(src, dst);

    // prep: split weights + input features into bf16 hi/lo
    wprep_kernel<<<288, 256>>>(Ws1, Wn1, Ws2, Wn2, Wout);
    fconv_kernel<<<FCB, 256>>>(feat);

    // layer 1
    gather_kernel<<<GAB, 256>>>(feat);
    mma_gemm_kernel<128, 4, true, true, true, true>
        <<<GB, 512, smem_bytes(128)>>>(p_feat_hi, p_feat_lo, p_B1_hi, p_B1_lo, b1,
                                       h1, p_h1_hi, p_h1_lo);

    // layer 2
    gather_kernel<<<GAB, 256>>>(h1);
    mma_gemm_kernel<128, 4, true, false, true, true>
        <<<GB, 512, smem_bytes(128)>>>(p_h1_hi, p_h1_lo, p_B2_hi, p_B2_lo, b2,
                                       nullptr, p_h2_hi, p_h2_lo);

    // output projection
    mma_gemm_kernel<64, 2, false, true, false, false>
        <<<GB, 512, smem_bytes(64)>>>(p_h2_hi, p_h2_lo, p_Bo_hi, p_Bo_lo, bout,
                                      out, nullptr, nullptr);
}

// round 8
// speedup vs baseline: 1.2768x; 1.0601x over previous
#include <cuda_runtime.h>
#include <cuda_bf16.h>
#include <cuda_fp16.h>
#include <cstdint>

#define N_NODES 100000
#define N_EDGES 1600000
#define D_IN 128
#define D_HID 128
#define N_CLASSES 64

// ---------------- device scratch (no dynamic alloc) ----------------
__device__ __align__(16) __half g_feat16[(size_t)N_NODES * D_IN];   // fp16 gather input L1
__device__ __align__(16) __half g_h1_16 [(size_t)N_NODES * D_HID];  // fp16 gather input L2
__device__ __align__(16) __nv_bfloat16 g_feat_hi[(size_t)N_NODES * D_IN];
__device__ __align__(16) __nv_bfloat16 g_feat_lo[(size_t)N_NODES * D_IN];
__device__ __align__(16) __nv_bfloat16 g_agg_hi [(size_t)N_NODES * D_HID];
__device__ __align__(16) __nv_bfloat16 g_agg_lo [(size_t)N_NODES * D_HID];
__device__ __align__(16) __nv_bfloat16 g_h1_hi  [(size_t)N_NODES * D_HID];
__device__ __align__(16) __nv_bfloat16 g_h1_lo  [(size_t)N_NODES * D_HID];
__device__ __align__(16) __nv_bfloat16 g_h2_hi  [(size_t)N_NODES * D_HID];
__device__ __align__(16) __nv_bfloat16 g_h2_lo  [(size_t)N_NODES * D_HID];
// transposed split weights, B[n][k]  (K=256 for layers, 128 for out)
__device__ __align__(16) __nv_bfloat16 g_B1_hi[128 * 256];
__device__ __align__(16) __nv_bfloat16 g_B1_lo[128 * 256];
__device__ __align__(16) __nv_bfloat16 g_B2_hi[128 * 256];
__device__ __align__(16) __nv_bfloat16 g_B2_lo[128 * 256];
__device__ __align__(16) __nv_bfloat16 g_Bo_hi[64 * 128];
__device__ __align__(16) __nv_bfloat16 g_Bo_lo[64 * 128];
// CSR
__device__ float    g_inv [N_NODES];
__device__ unsigned g_ideg[N_NODES];
__device__ unsigned g_off [N_NODES + 1];
__device__ unsigned g_cur [N_NODES];
__device__ int      g_esrc[N_EDGES];

// ---------------- helpers ----------------
__device__ __forceinline__ uint32_t smem_to_u32(const void* p) {
    uint32_t a;
    asm("{ .reg .u64 t; cvta.to.shared.u64 t, %1; cvt.u32.u64 %0, t; }" : "=r"(a) : "l"(p));
    return a;
}

__device__ __forceinline__ void ldsm_x4(uint32_t addr, uint32_t* r) {
    asm volatile("ldmatrix.sync.aligned.m8n8.x4.shared.b16 {%0,%1,%2,%3}, [%4];"
                 : "=r"(r[0]), "=r"(r[1]), "=r"(r[2]), "=r"(r[3]) : "r"(addr));
}

__device__ __forceinline__ void mma16816(float* c, const uint32_t* a,
                                         uint32_t b0, uint32_t b1) {
    asm volatile("mma.sync.aligned.m16n8k16.row.col.f32.bf16.bf16.f32 "
                 "{%0,%1,%2,%3}, {%4,%5,%6,%7}, {%8,%9}, {%0,%1,%2,%3};"
                 : "+f"(c[0]), "+f"(c[1]), "+f"(c[2]), "+f"(c[3])
                 : "r"(a[0]), "r"(a[1]), "r"(a[2]), "r"(a[3]), "r"(b0), "r"(b1));
}

__device__ __forceinline__ void split_bf16(float v, __nv_bfloat16& hi, __nv_bfloat16& lo) {
    hi = __float2bfloat16(v);
    lo = __float2bfloat16(v - __bfloat162float(hi));
}

// ---------------- CSR build ----------------
__global__ void zero_ideg_kernel() {
    int i = blockIdx.x * blockDim.x + threadIdx.x;
    if (i < N_NODES) g_ideg[i] = 0u;
}
__global__ void deg_kernel(const int* __restrict__ dst) {
    int e = blockIdx.x * blockDim.x + threadIdx.x;
    if (e < N_EDGES) atomicAdd(&g_ideg[dst[e]], 1u);
}
__global__ __launch_bounds__(1024)
void scan_kernel() {
    __shared__ unsigned sm[1024];
    const int t  = threadIdx.x;
    const int CH = (N_NODES + 1023) / 1024;
    int lo = t * CH;
    int hi = lo + CH; if (hi > N_NODES) hi = N_NODES;
    if (lo > N_NODES) lo = N_NODES;
    unsigned sum = 0;
    for (int i = lo; i < hi; ++i) sum += g_ideg[i];
    sm[t] = sum;
    __syncthreads();
    for (int d = 1; d < 1024; d <<= 1) {
        unsigned u = (t >= d) ? sm[t - d] : 0u;
        __syncthreads();
        sm[t] += u;
        __syncthreads();
    }
    unsigned off = sm[t] - sum;
    for (int i = lo; i < hi; ++i) {
        unsigned d = g_ideg[i];
        g_off[i] = off;
        g_cur[i] = off;
        g_inv[i] = 1.0f / fmaxf((float)d, 1.0f);
        off += d;
    }
    if (t == 1023) g_off[N_NODES] = sm[1023];
}
__global__ void fill_kernel(const int* __restrict__ src, const int* __restrict__ dst) {
    int e = blockIdx.x * blockDim.x + threadIdx.x;
    if (e < N_EDGES) {
        unsigned p = atomicAdd(&g_cur[dst[e]], 1u);
        g_esrc[p] = src[e];
    }
}

// ---------------- input/weight prep ----------------
// feat fp32 -> bf16 hi/lo (GEMM A) + fp16 (gather input)
__global__ void fconv_kernel(const float* __restrict__ f) {
    unsigned i = blockIdx.x * blockDim.x + threadIdx.x;   // over N_NODES*32 float4 units
    if (i >= (unsigned)N_NODES * 32u) return;
    float4 v = reinterpret_cast<const float4*>(f)[i];
    __nv_bfloat16 hx, lx, hy, ly, hz, lz, hw, lw;
    split_bf16(v.x, hx, lx); split_bf16(v.y, hy, ly);
    split_bf16(v.z, hz, lz); split_bf16(v.w, hw, lw);
    __nv_bfloat162 H0; H0.x = hx; H0.y = hy;
    __nv_bfloat162 H1; H1.x = hz; H1.y = hw;
    __nv_bfloat162 L0; L0.x = lx; L0.y = ly;
    __nv_bfloat162 L1; L1.x = lz; L1.y = lw;
    reinterpret_cast<__nv_bfloat162*>(g_feat_hi)[i * 2 + 0] = H0;
    reinterpret_cast<__nv_bfloat162*>(g_feat_hi)[i * 2 + 1] = H1;
    reinterpret_cast<__nv_bfloat162*>(g_feat_lo)[i * 2 + 0] = L0;
    reinterpret_cast<__nv_bfloat162*>(g_feat_lo)[i * 2 + 1] = L1;
    __half2 q0 = __floats2half2_rn(v.x, v.y);
    __half2 q1 = __floats2half2_rn(v.z, v.w);
    reinterpret_cast<__half2*>(g_feat16)[i * 2 + 0] = q0;
    reinterpret_cast<__half2*>(g_feat16)[i * 2 + 1] = q1;
}

__global__ void wprep_kernel(const float* __restrict__ Ws1, const float* __restrict__ Wn1,
                             const float* __restrict__ Ws2, const float* __restrict__ Wn2,
                             const float* __restrict__ Wo) {
    int i = blockIdx.x * blockDim.x + threadIdx.x;
    float v; __nv_bfloat16 *dh, *dl; int idx;
    if (i < 32768) {
        int n = i >> 8, k = i & 255;
        v = (k < 128) ? Ws1[k * 128 + n] : Wn1[(k - 128) * 128 + n];
        dh = g_B1_hi; dl = g_B1_lo; idx = i;
    } else if (i < 65536) {
        int j = i - 32768; int n = j >> 8, k = j & 255;
        v = (k < 128) ? Ws2[k * 128 + n] : Wn2[(k - 128) * 128 + n];
        dh = g_B2_hi; dl = g_B2_lo; idx = j;
    } else if (i < 73728) {
        int j = i - 65536; int n = j >> 7, k = j & 127;
        v = Wo[k * 64 + n];
        dh = g_Bo_hi; dl = g_Bo_lo; idx = j;
    } else return;
    __nv_bfloat16 h, l;
    split_bf16(v, h, l);
    dh[idx] = h; dl[idx] = l;
}

// ---------------- gather-mean (fp16 input): one warp per dst node ----------
// Lane covers 4 cols (8 bytes). Unroll 8 neighbors for MLP.
__global__ __launch_bounds__(256)
void gather_kernel(const __half* __restrict__ h) {
    unsigned warp = (blockIdx.x * blockDim.x + threadIdx.x) >> 5;
    if (warp >= N_NODES) return;
    const unsigned lane = threadIdx.x & 31;
    unsigned start = g_off[warp];
    unsigned end   = g_off[warp + 1];

    float ax = 0.f, ay = 0.f, az = 0.f, aw = 0.f;
    const uint2* __restrict__ hv = reinterpret_cast<const uint2*>(h);
    unsigned i = start;
    for (; i + 8 <= end; i += 8) {
        uint2 u[8];
#pragma unroll
        for (int q = 0; q < 8; ++q) {
            int s = __ldg(&g_esrc[i + q]);
            u[q] = hv[(size_t)s * 32 + lane];
        }
#pragma unroll
        for (int q = 0; q < 8; ++q) {
            float2 f0 = __half22float2(*reinterpret_cast<__half2*>(&u[q].x));
            float2 f1 = __half22float2(*reinterpret_cast<__half2*>(&u[q].y));
            ax += f0.x; ay += f0.y; az += f1.x; aw += f1.y;
        }
    }
    for (; i < end; ++i) {
        int s = __ldg(&g_esrc[i]);
        uint2 u = hv[(size_t)s * 32 + lane];
        float2 f0 = __half22float2(*reinterpret_cast<__half2*>(&u.x));
        float2 f1 = __half22float2(*reinterpret_cast<__half2*>(&u.y));
        ax += f0.x; ay += f0.y; az += f1.x; aw += f1.y;
    }
    float sc = g_inv[warp];
    float rx = ax * sc, ry = ay * sc, rz = az * sc, rw = aw * sc;

    __nv_bfloat16 hx, lx, hy, ly, hz, lz, hw, lw;
    split_bf16(rx, hx, lx); split_bf16(ry, hy, ly);
    split_bf16(rz, hz, lz); split_bf16(rw, hw, lw);
    size_t base = (size_t)warp * D_HID + lane * 4;
    __nv_bfloat162 H0; H0.x = hx; H0.y = hy;
    __nv_bfloat162 H1; H1.x = hz; H1.y = hw;
    __nv_bfloat162 L0; L0.x = lx; L0.y = ly;
    __nv_bfloat162 L1; L1.x = lz; L1.y = lw;
    *reinterpret_cast<__nv_bfloat162*>(g_agg_hi + base)     = H0;
    *reinterpret_cast<__nv_bfloat162*>(g_agg_hi + base + 2) = H1;
    *reinterpret_cast<__nv_bfloat162*>(g_agg_lo + base)     = L0;
    *reinterpret_cast<__nv_bfloat162*>(g_agg_lo + base + 2) = L1;
}

// ---------------- mma.sync split-bf16 GEMM ----------------
// C[128 x BN] = sum over NCHUNKS chunks of 64 K-cols: Ah*Bh + Ah*Bl + Al*Bh
// DUALSRC: chunks 0-1 from (A_hi,A_lo), chunks 2-3 from g_agg_hi/lo.
// 512 threads = 16 warps; warp tile 32x32; smem rows padded to 144B.
constexpr int ROWB = 144;                       // 64 bf16 (128B) + 16B pad
constexpr int smem_bytes(int BN) { return 2 * 128 * ROWB + 2 * BN * ROWB; }

template<int BN, int NCHUNKS, bool DUALSRC, bool WF32, bool WF16, bool WBF16, bool RELU>
__global__ __launch_bounds__(512)
void mma_gemm_kernel(const __nv_bfloat16* __restrict__ A_hi,
                     const __nv_bfloat16* __restrict__ A_lo,
                     const __nv_bfloat16* __restrict__ B_hi,
                     const __nv_bfloat16* __restrict__ B_lo,
                     const float* __restrict__ bias,
                     float* __restrict__ outf,
                     __half* __restrict__ outh,
                     __nv_bfloat16* __restrict__ out_hi,
                     __nv_bfloat16* __restrict__ out_lo) {
    extern __shared__ unsigned char dynsm[];
    constexpr int OFF_A_HI = 0;
    constexpr int OFF_A_LO = 128 * ROWB;
    constexpr int OFF_B_HI = 2 * 128 * ROWB;
    constexpr int OFF_B_LO = OFF_B_HI + BN * ROWB;
    constexpr int KTOT = NCHUNKS * 64;
    constexpr int NW = BN / 32;                 // warps along N

    const int tid  = threadIdx.x;
    const int wid  = tid >> 5;
    const int lane = tid & 31;
    const int rowBase = blockIdx.x * 128;
    const uint32_t sbase = smem_to_u32(dynsm);

    const bool active = wid < 4 * NW;
    const int warpM = wid / NW;                 // 0..3
    const int warpN = wid % NW;                 // 0..NW-1

    float acc[2][4][4];
#pragma unroll
    for (int mi = 0; mi < 2; ++mi)
#pragma unroll
        for (int j = 0; j < 4; ++j)
#pragma unroll
            for (int c = 0; c < 4; ++c) acc[mi][j][c] = 0.f;

    // per-lane ldmatrix row mapping: m = lane/8, r = lane%8
    const int lm_m = lane >> 3;
    const int lm_r = lane & 7;
    const int lm_rowoff = (lm_m & 1) * 8 + lm_r;     // row within 16-row tile
    const int lm_coloff = (lm_m >> 1) * 16;          // byte offset within k16

    for (int ch = 0; ch < NCHUNKS; ++ch) {
        // ---- stage A chunk (128 x 64 bf16 hi/lo)
        for (int u = tid; u < 1024; u += 512) {
            int r = u >> 3, c = u & 7;
            int gr = rowBase + r;
            uint4 vh = make_uint4(0, 0, 0, 0), vl = make_uint4(0, 0, 0, 0);
            if (gr < N_NODES) {
                const __nv_bfloat16 *ph, *pl;
                size_t off;
                if (!DUALSRC || ch < 2) {
                    off = (size_t)gr * 128 + ch * 64 + c * 8;
                    ph = A_hi; pl = A_lo;
                } else {
                    off = (size_t)gr * 128 + (ch - 2) * 64 + c * 8;
                    ph = g_agg_hi; pl = g_agg_lo;
                }
                vh = *reinterpret_cast<const uint4*>(ph + off);
                vl = *reinterpret_cast<const uint4*>(pl + off);
            }
            *reinterpret_cast<uint4*>(dynsm + OFF_A_HI + r * ROWB + c * 16) = vh;
            *reinterpret_cast<uint4*>(dynsm + OFF_A_LO + r * ROWB + c * 16) = vl;
        }
        // ---- stage B chunk (BN x 64 bf16 hi/lo), source layout [n][KTOT]
        for (int u = tid; u < BN * 8; u += 512) {
            int n = u >> 3, c = u & 7;
            size_t off = (size_t)n * KTOT + ch * 64 + c * 8;
            *reinterpret_cast<uint4*>(dynsm + OFF_B_HI + n * ROWB + c * 16) =
                *reinterpret_cast<const uint4*>(B_hi + off);
            *reinterpret_cast<uint4*>(dynsm + OFF_B_LO + n * ROWB + c * 16) =
                *reinterpret_cast<const uint4*>(B_lo + off);
        }
        __syncthreads();

        if (active) {
#pragma unroll
            for (int ks = 0; ks < 4; ++ks) {
                const int kb = ks * 32 + lm_coloff;       // byte offset in row
                uint32_t ah[2][4], al[2][4];
#pragma unroll
                for (int mi = 0; mi < 2; ++mi) {
                    int row = warpM * 32 + mi * 16 + lm_rowoff;
                    ldsm_x4(sbase + OFF_A_HI + row * ROWB + kb, ah[mi]);
                    ldsm_x4(sbase + OFF_A_LO + row * ROWB + kb, al[mi]);
                }
                uint32_t bh[2][4], bl[2][4];
#pragma unroll
                for (int nb = 0; nb < 2; ++nb) {
                    int nrow = warpN * 32 + nb * 16 + lm_rowoff;
                    ldsm_x4(sbase + OFF_B_HI + nrow * ROWB + kb, bh[nb]);
                    ldsm_x4(sbase + OFF_B_LO + nrow * ROWB + kb, bl[nb]);
                }
#pragma unroll
                for (int mi = 0; mi < 2; ++mi)
#pragma unroll
                    for (int j = 0; j < 4; ++j) {
                        const int nb = j >> 1, jj = j & 1;
                        mma16816(acc[mi][j], ah[mi], bh[nb][jj], bh[nb][jj + 2]);
                        mma16816(acc[mi][j], ah[mi], bl[nb][jj], bl[nb][jj + 2]);
                        mma16816(acc[mi][j], al[mi], bh[nb][jj], bh[nb][jj + 2]);
                    }
            }
        }
        __syncthreads();
    }

    // ---- epilogue
    if (active) {
        const int rlo  = rowBase + warpM * 32 + (lane >> 2);
        const int colw = warpN * 32 + 2 * (lane & 3);
#pragma unroll
        for (int mi = 0; mi < 2; ++mi) {
#pragma unroll
            for (int j = 0; j < 4; ++j) {
                const int col = colw + j * 8;
                const float b0 = __ldg(&bias[col]);
                const float b1 = __ldg(&bias[col + 1]);
#pragma unroll
                for (int half = 0; half < 2; ++half) {
                    int r = rlo + mi * 16 + half * 8;
                    if (r >= N_NODES) continue;
                    float v0 = acc[mi][j][2 * half + 0] + b0;
                    float v1 = acc[mi][j][2 * half + 1] + b1;
                    if (RELU) { v0 = fmaxf(v0, 0.f); v1 = fmaxf(v1, 0.f); }
                    if (WF32) {
                        float2 f2; f2.x = v0; f2.y = v1;
                        *reinterpret_cast<float2*>(outf + (size_t)r * BN + col) = f2;
                    }
                    if (WF16) {
                        __half2 hh = __floats2half2_rn(v0, v1);
                        *reinterpret_cast<__half2*>(outh + (size_t)r * BN + col) = hh;
                    }
                    if (WBF16) {
                        __nv_bfloat16 h0, l0, h1, l1;
                        split_bf16(v0, h0, l0);
                        split_bf16(v1, h1, l1);
                        __nv_bfloat162 H; H.x = h0; H.y = h1;
                        __nv_bfloat162 L; L.x = l0; L.y = l1;
                        *reinterpret_cast<__nv_bfloat162*>(out_hi + (size_t)r * BN + col) = H;
                        *reinterpret_cast<__nv_bfloat162*>(out_lo + (size_t)r * BN + col) = L;
                    }
                }
            }
        }
    }
}

// ---------------- launch ----------------
extern "C" void kernel_launch(void* const* d_in, const int* in_sizes, int n_in,
                              void* d_out, int out_size) {
    const float* feat = (const float*)d_in[0];
    const int*   src  = (const int*)  d_in[1];
    const int*   dst  = (const int*)  d_in[2];
    const float* Ws1  = (const float*)d_in[3];
    const float* Wn1  = (const float*)d_in[4];
    const float* b1   = (const float*)d_in[5];
    const float* Ws2  = (const float*)d_in[6];
    const float* Wn2  = (const float*)d_in[7];
    const float* b2   = (const float*)d_in[8];
    const float* Wout = (const float*)d_in[9];
    const float* bout = (const float*)d_in[10];
    float* out = (float*)d_out;

    __half *p_feat16, *p_h1_16;
    __nv_bfloat16 *p_feat_hi, *p_feat_lo, *p_h1_hi, *p_h1_lo, *p_h2_hi, *p_h2_lo;
    __nv_bfloat16 *p_B1_hi, *p_B1_lo, *p_B2_hi, *p_B2_lo, *p_Bo_hi, *p_Bo_lo;
    cudaGetSymbolAddress((void**)&p_feat16, g_feat16);
    cudaGetSymbolAddress((void**)&p_h1_16, g_h1_16);
    cudaGetSymbolAddress((void**)&p_feat_hi, g_feat_hi);
    cudaGetSymbolAddress((void**)&p_feat_lo, g_feat_lo);
    cudaGetSymbolAddress((void**)&p_h1_hi, g_h1_hi);
    cudaGetSymbolAddress((void**)&p_h1_lo, g_h1_lo);
    cudaGetSymbolAddress((void**)&p_h2_hi, g_h2_hi);
    cudaGetSymbolAddress((void**)&p_h2_lo, g_h2_lo);
    cudaGetSymbolAddress((void**)&p_B1_hi, g_B1_hi);
    cudaGetSymbolAddress((void**)&p_B1_lo, g_B1_lo);
    cudaGetSymbolAddress((void**)&p_B2_hi, g_B2_hi);
    cudaGetSymbolAddress((void**)&p_B2_lo, g_B2_lo);
    cudaGetSymbolAddress((void**)&p_Bo_hi, g_Bo_hi);
    cudaGetSymbolAddress((void**)&p_Bo_lo, g_Bo_lo);
    cudaFuncSetAttribute(mma_gemm_kernel<128, 4, true, false, true,  true,  true>,
                         cudaFuncAttributeMaxDynamicSharedMemorySize, smem_bytes(128));
    cudaFuncSetAttribute(mma_gemm_kernel<128, 4, true, false, false, true,  true>,
                         cudaFuncAttributeMaxDynamicSharedMemorySize, smem_bytes(128));
    cudaFuncSetAttribute(mma_gemm_kernel<64, 2, false, true,  false, false, false>,
                         cudaFuncAttributeMaxDynamicSharedMemorySize, smem_bytes(64));

    const int IB  = (N_NODES + 255) / 256;
    const int EB  = (N_EDGES + 255) / 256;
    const int GAB = (N_NODES * 32 + 255) / 256;
    const int GB  = (N_NODES + 127) / 128;               // 782

    // CSR build
    zero_ideg_kernel<<<IB, 256>>>();
    deg_kernel<<<EB, 256>>>(dst);
    scan_kernel<<<1, 1024>>>();
    fill_kernel<<<EB, 256>>>(src, dst);

    // prep: split weights + input features into bf16 hi/lo + fp16
    wprep_kernel<<<288, 256>>>(Ws1, Wn1, Ws2, Wn2, Wout);
    fconv_kernel<<<GAB, 256>>>(feat);

    // layer 1
    gather_kernel<<<GAB, 256>>>(p_feat16);
    mma_gemm_kernel<128, 4, true, false, true, true, true>
        <<<GB, 512, smem_bytes(128)>>>(p_feat_hi, p_feat_lo, p_B1_hi, p_B1_lo, b1,
                                       nullptr, p_h1_16, p_h1_hi, p_h1_lo);

    // layer 2
    gather_kernel<<<GAB, 256>>>(p_h1_16);
    mma_gemm_kernel<128, 4, true, false, false, true, true>
        <<<GB, 512, smem_bytes(128)>>>(p_h1_hi, p_h1_lo, p_B2_hi, p_B2_lo, b2,
                                       nullptr, nullptr, p_h2_hi, p_h2_lo);

    // output projection
    mma_gemm_kernel<64, 2, false, true, false, false, false>
        <<<GB, 512, smem_bytes(64)>>>(p_h2_hi, p_h2_lo, p_Bo_hi, p_Bo_lo, bout,
                                      out, nullptr, nullptr, nullptr);
}

// round 9
// speedup vs baseline: 1.5299x; 1.1982x over previous
#include <cuda_runtime.h>
#include <cuda_bf16.h>
#include <cuda_fp16.h>
#include <cstdint>

#define N_NODES 100000
#define N_EDGES 1600000
#define D_IN 128
#define D_HID 128
#define N_CLASSES 64

// ---------------- device scratch (no dynamic alloc) ----------------
// Single fp16 copy of every activation; bf16 hi/lo produced on the fly in GEMMs.
__device__ __align__(16) __half g_feat16[(size_t)N_NODES * D_IN];
__device__ __align__(16) __half g_agg16 [(size_t)N_NODES * D_HID];
__device__ __align__(16) __half g_h1_16 [(size_t)N_NODES * D_HID];
__device__ __align__(16) __half g_h2_16 [(size_t)N_NODES * D_HID];
// transposed split weights, B[n][k]  (K=256 for layers, 128 for out) — exact split of fp32
__device__ __align__(16) __nv_bfloat16 g_B1_hi[128 * 256];
__device__ __align__(16) __nv_bfloat16 g_B1_lo[128 * 256];
__device__ __align__(16) __nv_bfloat16 g_B2_hi[128 * 256];
__device__ __align__(16) __nv_bfloat16 g_B2_lo[128 * 256];
__device__ __align__(16) __nv_bfloat16 g_Bo_hi[64 * 128];
__device__ __align__(16) __nv_bfloat16 g_Bo_lo[64 * 128];
// CSR
__device__ float    g_inv [N_NODES];
__device__ unsigned g_ideg[N_NODES];
__device__ unsigned g_off [N_NODES + 1];
__device__ unsigned g_cur [N_NODES];
__device__ int      g_esrc[N_EDGES];

// ---------------- helpers ----------------
__device__ __forceinline__ uint32_t smem_to_u32(const void* p) {
    uint32_t a;
    asm("{ .reg .u64 t; cvta.to.shared.u64 t, %1; cvt.u32.u64 %0, t; }" : "=r"(a) : "l"(p));
    return a;
}

__device__ __forceinline__ void ldsm_x4(uint32_t addr, uint32_t* r) {
    asm volatile("ldmatrix.sync.aligned.m8n8.x4.shared.b16 {%0,%1,%2,%3}, [%4];"
                 : "=r"(r[0]), "=r"(r[1]), "=r"(r[2]), "=r"(r[3]) : "r"(addr));
}

__device__ __forceinline__ void mma16816(float* c, const uint32_t* a,
                                         uint32_t b0, uint32_t b1) {
    asm volatile("mma.sync.aligned.m16n8k16.row.col.f32.bf16.bf16.f32 "
                 "{%0,%1,%2,%3}, {%4,%5,%6,%7}, {%8,%9}, {%0,%1,%2,%3};"
                 : "+f"(c[0]), "+f"(c[1]), "+f"(c[2]), "+f"(c[3])
                 : "r"(a[0]), "r"(a[1]), "r"(a[2]), "r"(a[3]), "r"(b0), "r"(b1));
}

__device__ __forceinline__ void split_bf16(float v, __nv_bfloat16& hi, __nv_bfloat16& lo) {
    hi = __float2bfloat16(v);
    lo = __float2bfloat16(v - __bfloat162float(hi));
}

// 8 fp16 (uint4) -> 8 bf16 hi (uint4) + 8 bf16 lo (uint4). Exact for fp16 inputs.
__device__ __forceinline__ void cvt_h8_split(const uint4& raw, uint4& hi4, uint4& lo4) {
    const __half2* hp = reinterpret_cast<const __half2*>(&raw);
    uint32_t H[4], L[4];
#pragma unroll
    for (int i = 0; i < 4; ++i) {
        float2 f = __half22float2(hp[i]);
        __nv_bfloat16 h0, l0, h1, l1;
        split_bf16(f.x, h0, l0);
        split_bf16(f.y, h1, l1);
        __nv_bfloat162 Hb; Hb.x = h0; Hb.y = h1;
        __nv_bfloat162 Lb; Lb.x = l0; Lb.y = l1;
        H[i] = *reinterpret_cast<uint32_t*>(&Hb);
        L[i] = *reinterpret_cast<uint32_t*>(&Lb);
    }
    hi4 = make_uint4(H[0], H[1], H[2], H[3]);
    lo4 = make_uint4(L[0], L[1], L[2], L[3]);
}

// ---------------- CSR build ----------------
__global__ void zero_ideg_kernel() {
    int i = blockIdx.x * blockDim.x + threadIdx.x;
    if (i < N_NODES) g_ideg[i] = 0u;
}
__global__ void deg_kernel(const int* __restrict__ dst) {
    int e = blockIdx.x * blockDim.x + threadIdx.x;
    if (e < N_EDGES) atomicAdd(&g_ideg[dst[e]], 1u);
}
__global__ __launch_bounds__(1024)
void scan_kernel() {
    __shared__ unsigned sm[1024];
    const int t  = threadIdx.x;
    const int CH = (N_NODES + 1023) / 1024;
    int lo = t * CH;
    int hi = lo + CH; if (hi > N_NODES) hi = N_NODES;
    if (lo > N_NODES) lo = N_NODES;
    unsigned sum = 0;
    for (int i = lo; i < hi; ++i) sum += g_ideg[i];
    sm[t] = sum;
    __syncthreads();
    for (int d = 1; d < 1024; d <<= 1) {
        unsigned u = (t >= d) ? sm[t - d] : 0u;
        __syncthreads();
        sm[t] += u;
        __syncthreads();
    }
    unsigned off = sm[t] - sum;
    for (int i = lo; i < hi; ++i) {
        unsigned d = g_ideg[i];
        g_off[i] = off;
        g_cur[i] = off;
        g_inv[i] = 1.0f / fmaxf((float)d, 1.0f);
        off += d;
    }
    if (t == 1023) g_off[N_NODES] = sm[1023];
}
__global__ void fill_kernel(const int* __restrict__ src, const int* __restrict__ dst) {
    int e = blockIdx.x * blockDim.x + threadIdx.x;
    if (e < N_EDGES) {
        unsigned p = atomicAdd(&g_cur[dst[e]], 1u);
        g_esrc[p] = src[e];
    }
}

// ---------------- input/weight prep ----------------
__global__ void fconv_kernel(const float* __restrict__ f) {
    unsigned i = blockIdx.x * blockDim.x + threadIdx.x;   // over N_NODES*32 float4 units
    if (i >= (unsigned)N_NODES * 32u) return;
    float4 v = reinterpret_cast<const float4*>(f)[i];
    __half2 q0 = __floats2half2_rn(v.x, v.y);
    __half2 q1 = __floats2half2_rn(v.z, v.w);
    reinterpret_cast<__half2*>(g_feat16)[i * 2 + 0] = q0;
    reinterpret_cast<__half2*>(g_feat16)[i * 2 + 1] = q1;
}

__global__ void wprep_kernel(const float* __restrict__ Ws1, const float* __restrict__ Wn1,
                             const float* __restrict__ Ws2, const float* __restrict__ Wn2,
                             const float* __restrict__ Wo) {
    int i = blockIdx.x * blockDim.x + threadIdx.x;
    float v; __nv_bfloat16 *dh, *dl; int idx;
    if (i < 32768) {
        int n = i >> 8, k = i & 255;
        v = (k < 128) ? Ws1[k * 128 + n] : Wn1[(k - 128) * 128 + n];
        dh = g_B1_hi; dl = g_B1_lo; idx = i;
    } else if (i < 65536) {
        int j = i - 32768; int n = j >> 8, k = j & 255;
        v = (k < 128) ? Ws2[k * 128 + n] : Wn2[(k - 128) * 128 + n];
        dh = g_B2_hi; dl = g_B2_lo; idx = j;
    } else if (i < 73728) {
        int j = i - 65536; int n = j >> 7, k = j & 127;
        v = Wo[k * 64 + n];
        dh = g_Bo_hi; dl = g_Bo_lo; idx = j;
    } else return;
    __nv_bfloat16 h, l;
    split_bf16(v, h, l);
    dh[idx] = h; dl[idx] = l;
}

// ---------------- gather-mean (fp16 in, fp16 out): one warp per dst node ----
__global__ __launch_bounds__(256)
void gather_kernel(const __half* __restrict__ h) {
    unsigned warp = (blockIdx.x * blockDim.x + threadIdx.x) >> 5;
    if (warp >= N_NODES) return;
    const unsigned lane = threadIdx.x & 31;
    unsigned start = g_off[warp];
    unsigned end   = g_off[warp + 1];

    float ax = 0.f, ay = 0.f, az = 0.f, aw = 0.f;
    const uint2* __restrict__ hv = reinterpret_cast<const uint2*>(h);
    unsigned i = start;
    for (; i + 8 <= end; i += 8) {
        uint2 u[8];
#pragma unroll
        for (int q = 0; q < 8; ++q) {
            int s = __ldg(&g_esrc[i + q]);
            u[q] = hv[(size_t)s * 32 + lane];
        }
#pragma unroll
        for (int q = 0; q < 8; ++q) {
            float2 f0 = __half22float2(*reinterpret_cast<__half2*>(&u[q].x));
            float2 f1 = __half22float2(*reinterpret_cast<__half2*>(&u[q].y));
            ax += f0.x; ay += f0.y; az += f1.x; aw += f1.y;
        }
    }
    for (; i < end; ++i) {
        int s = __ldg(&g_esrc[i]);
        uint2 u = hv[(size_t)s * 32 + lane];
        float2 f0 = __half22float2(*reinterpret_cast<__half2*>(&u.x));
        float2 f1 = __half22float2(*reinterpret_cast<__half2*>(&u.y));
        ax += f0.x; ay += f0.y; az += f1.x; aw += f1.y;
    }
    float sc = g_inv[warp];
    __half2 o0 = __floats2half2_rn(ax * sc, ay * sc);
    __half2 o1 = __floats2half2_rn(az * sc, aw * sc);
    uint2 o;
    o.x = *reinterpret_cast<uint32_t*>(&o0);
    o.y = *reinterpret_cast<uint32_t*>(&o1);
    reinterpret_cast<uint2*>(g_agg16)[(size_t)warp * 32 + lane] = o;
}

// ---------------- mma.sync split-bf16 GEMM, fp16 activations ----------------
// C[128 x BN] = sum over NCHUNKS chunks of 64 K-cols: Ah*Bh + Ah*Bl + Al*Bh
// A source fp16; split to bf16 hi/lo during smem staging (exact).
// DUALSRC: chunks 0-1 self (A16), chunks 2-3 neighbor (g_agg16).
// Software pipeline: prefetch next chunk's global data into regs during mma.
constexpr int ROWB = 144;                       // 64 bf16 (128B) + 16B pad
constexpr int smem_bytes(int BN) { return 2 * 128 * ROWB + 2 * BN * ROWB; }

template<int BN, int NCHUNKS, bool DUALSRC, bool WF32, bool WF16, bool RELU>
__global__ __launch_bounds__(512)
void mma_gemm_kernel(const __half* __restrict__ A16,
                     const __nv_bfloat16* __restrict__ B_hi,
                     const __nv_bfloat16* __restrict__ B_lo,
                     const float* __restrict__ bias,
                     float* __restrict__ outf,
                     __half* __restrict__ outh) {
    extern __shared__ unsigned char dynsm[];
    constexpr int OFF_A_HI = 0;
    constexpr int OFF_A_LO = 128 * ROWB;
    constexpr int OFF_B_HI = 2 * 128 * ROWB;
    constexpr int OFF_B_LO = OFF_B_HI + BN * ROWB;
    constexpr int KTOT = NCHUNKS * 64;
    constexpr int NW = BN / 32;                 // warps along N
    constexpr int NB_IT = BN * 8 / 512;         // B stage iters per thread (2 for BN=128, 1 for 64)

    const int tid  = threadIdx.x;
    const int wid  = tid >> 5;
    const int lane = tid & 31;
    const int rowBase = blockIdx.x * 128;
    const uint32_t sbase = smem_to_u32(dynsm);

    const bool active = wid < 4 * NW;
    const int warpM = wid / NW;
    const int warpN = wid % NW;

    float acc[2][4][4];
#pragma unroll
    for (int mi = 0; mi < 2; ++mi)
#pragma unroll
        for (int j = 0; j < 4; ++j)
#pragma unroll
            for (int c = 0; c < 4; ++c) acc[mi][j][c] = 0.f;

    const int lm_m = lane >> 3;
    const int lm_r = lane & 7;
    const int lm_rowoff = (lm_m & 1) * 8 + lm_r;
    const int lm_coloff = (lm_m >> 1) * 16;

    // ---- prefetch registers
    uint4 aRaw[2];
    uint4 bH[NB_IT], bL[NB_IT];

    // loader: chunk -> regs
    auto load_chunk = [&](int ch) {
#pragma unroll
        for (int l = 0; l < 2; ++l) {
            int u = tid + l * 512;
            int r = u >> 3, c = u & 7;
            int gr = rowBase + r;
            uint4 v = make_uint4(0, 0, 0, 0);
            if (gr < N_NODES) {
                const __half* src = (!DUALSRC || ch < 2) ? A16 : g_agg16;
                int koff = (DUALSRC ? (ch & 1) : ch) * 64;
                v = *reinterpret_cast<const uint4*>(src + (size_t)gr * 128 + koff + c * 8);
            }
            aRaw[l] = v;
        }
#pragma unroll
        for (int l = 0; l < NB_IT; ++l) {
            int u = tid + l * 512;
            int n = u >> 3, c = u & 7;
            size_t off = (size_t)n * KTOT + ch * 64 + c * 8;
            bH[l] = *reinterpret_cast<const uint4*>(B_hi + off);
            bL[l] = *reinterpret_cast<const uint4*>(B_lo + off);
        }
    };
    // storer: regs -> smem (A converted to bf16 hi/lo)
    auto store_chunk = [&]() {
#pragma unroll
        for (int l = 0; l < 2; ++l) {
            int u = tid + l * 512;
            int r = u >> 3, c = u & 7;
            uint4 hi4, lo4;
            cvt_h8_split(aRaw[l], hi4, lo4);
            *reinterpret_cast<uint4*>(dynsm + OFF_A_HI + r * ROWB + c * 16) = hi4;
            *reinterpret_cast<uint4*>(dynsm + OFF_A_LO + r * ROWB + c * 16) = lo4;
        }
#pragma unroll
        for (int l = 0; l < NB_IT; ++l) {
            int u = tid + l * 512;
            int n = u >> 3, c = u & 7;
            *reinterpret_cast<uint4*>(dynsm + OFF_B_HI + n * ROWB + c * 16) = bH[l];
            *reinterpret_cast<uint4*>(dynsm + OFF_B_LO + n * ROWB + c * 16) = bL[l];
        }
    };

    load_chunk(0);
    for (int ch = 0; ch < NCHUNKS; ++ch) {
        store_chunk();
        __syncthreads();
        if (ch + 1 < NCHUNKS) load_chunk(ch + 1);   // latency overlaps mma below

        if (active) {
#pragma unroll
            for (int ks = 0; ks < 4; ++ks) {
                const int kb = ks * 32 + lm_coloff;
                uint32_t ah[2][4], al[2][4];
#pragma unroll
                for (int mi = 0; mi < 2; ++mi) {
                    int row = warpM * 32 + mi * 16 + lm_rowoff;
                    ldsm_x4(sbase + OFF_A_HI + row * ROWB + kb, ah[mi]);
                    ldsm_x4(sbase + OFF_A_LO + row * ROWB + kb, al[mi]);
                }
                uint32_t bh[2][4], bl[2][4];
#pragma unroll
                for (int nb = 0; nb < 2; ++nb) {
                    int nrow = warpN * 32 + nb * 16 + lm_rowoff;
                    ldsm_x4(sbase + OFF_B_HI + nrow * ROWB + kb, bh[nb]);
                    ldsm_x4(sbase + OFF_B_LO + nrow * ROWB + kb, bl[nb]);
                }
#pragma unroll
                for (int mi = 0; mi < 2; ++mi)
#pragma unroll
                    for (int j = 0; j < 4; ++j) {
                        const int nb = j >> 1, jj = j & 1;
                        mma16816(acc[mi][j], ah[mi], bh[nb][jj], bh[nb][jj + 2]);
                        mma16816(acc[mi][j], ah[mi], bl[nb][jj], bl[nb][jj + 2]);
                        mma16816(acc[mi][j], al[mi], bh[nb][jj], bh[nb][jj + 2]);
                    }
            }
        }
        __syncthreads();
    }

    // ---- epilogue
    if (active) {
        const int rlo  = rowBase + warpM * 32 + (lane >> 2);
        const int colw = warpN * 32 + 2 * (lane & 3);
#pragma unroll
        for (int mi = 0; mi < 2; ++mi) {
#pragma unroll
            for (int j = 0; j < 4; ++j) {
                const int col = colw + j * 8;
                const float b0 = __ldg(&bias[col]);
                const float b1 = __ldg(&bias[col + 1]);
#pragma unroll
                for (int half = 0; half < 2; ++half) {
                    int r = rlo + mi * 16 + half * 8;
                    if (r >= N_NODES) continue;
                    float v0 = acc[mi][j][2 * half + 0] + b0;
                    float v1 = acc[mi][j][2 * half + 1] + b1;
                    if (RELU) { v0 = fmaxf(v0, 0.f); v1 = fmaxf(v1, 0.f); }
                    if (WF32) {
                        float2 f2; f2.x = v0; f2.y = v1;
                        *reinterpret_cast<float2*>(outf + (size_t)r * BN + col) = f2;
                    }
                    if (WF16) {
                        __half2 hh = __floats2half2_rn(v0, v1);
                        *reinterpret_cast<__half2*>(outh + (size_t)r * BN + col) = hh;
                    }
                }
            }
        }
    }
}

// ---------------- launch ----------------
extern "C" void kernel_launch(void* const* d_in, const int* in_sizes, int n_in,
                              void* d_out, int out_size) {
    const float* feat = (const float*)d_in[0];
    const int*   src  = (const int*)  d_in[1];
    const int*   dst  = (const int*)  d_in[2];
    const float* Ws1  = (const float*)d_in[3];
    const float* Wn1  = (const float*)d_in[4];
    const float* b1   = (const float*)d_in[5];
    const float* Ws2  = (const float*)d_in[6];
    const float* Wn2  = (const float*)d_in[7];
    const float* b2   = (const float*)d_in[8];
    const float* Wout = (const float*)d_in[9];
    const float* bout = (const float*)d_in[10];
    float* out = (float*)d_out;

    __half *p_feat16, *p_h1_16, *p_h2_16;
    __nv_bfloat16 *p_B1_hi, *p_B1_lo, *p_B2_hi, *p_B2_lo, *p_Bo_hi, *p_Bo_lo;
    cudaGetSymbolAddress((void**)&p_feat16, g_feat16);
    cudaGetSymbolAddress((void**)&p_h1_16, g_h1_16);
    cudaGetSymbolAddress((void**)&p_h2_16, g_h2_16);
    cudaGetSymbolAddress((void**)&p_B1_hi, g_B1_hi);
    cudaGetSymbolAddress((void**)&p_B1_lo, g_B1_lo);
    cudaGetSymbolAddress((void**)&p_B2_hi, g_B2_hi);
    cudaGetSymbolAddress((void**)&p_B2_lo, g_B2_lo);
    cudaGetSymbolAddress((void**)&p_Bo_hi, g_Bo_hi);
    cudaGetSymbolAddress((void**)&p_Bo_lo, g_Bo_lo);
    cudaFuncSetAttribute(mma_gemm_kernel<128, 4, true, false, true, true>,
                         cudaFuncAttributeMaxDynamicSharedMemorySize, smem_bytes(128));
    cudaFuncSetAttribute(mma_gemm_kernel<64, 2, false, true, false, false>,
                         cudaFuncAttributeMaxDynamicSharedMemorySize, smem_bytes(64));

    const int IB  = (N_NODES + 255) / 256;
    const int EB  = (N_EDGES + 255) / 256;
    const int GAB = (N_NODES * 32 + 255) / 256;
    const int GB  = (N_NODES + 127) / 128;               // 782

    // CSR build
    zero_ideg_kernel<<<IB, 256>>>();
    deg_kernel<<<EB, 256>>>(dst);
    scan_kernel<<<1, 1024>>>();
    fill_kernel<<<EB, 256>>>(src, dst);

    // prep
    wprep_kernel<<<288, 256>>>(Ws1, Wn1, Ws2, Wn2, Wout);
    fconv_kernel<<<GAB, 256>>>(feat);

    // layer 1
    gather_kernel<<<GAB, 256>>>(p_feat16);
    mma_gemm_kernel<128, 4, true, false, true, true>
        <<<GB, 512, smem_bytes(128)>>>(p_feat16, p_B1_hi, p_B1_lo, b1, nullptr, p_h1_16);

    // layer 2
    gather_kernel<<<GAB, 256>>>(p_h1_16);
    mma_gemm_kernel<128, 4, true, false, true, true>
        <<<GB, 512, smem_bytes(128)>>>(p_h1_16, p_B2_hi, p_B2_lo, b2, nullptr, p_h2_16);

    // output projection
    mma_gemm_kernel<64, 2, false, true, false, false>
        <<<GB, 512, smem_bytes(64)>>>(p_h2_16, p_Bo_hi, p_Bo_lo, bout, out, nullptr);
}